// round 4
// baseline (speedup 1.0000x reference)
#include <cuda_runtime.h>
#include <cstdint>

#define BATCH   1024
#define FDIM    2048
#define LDIM    80
#define EDIM    512
#define IN_DIM  2560
#define ODIM    2048
#define NEXP    8

// GEMM config
#define BM 128
#define BN 128
#define BK 32
#define STAGES 4
#define ITER_PER_E (IN_DIM / BK)     // 80
#define NIT (NEXP * ITER_PER_E)      // 640
#define A_STAGE_F 4096               // 128x32 floats
#define B_ROW_F   136                // 128 + 8 pad
#define B_STAGE_F (BK * B_ROW_F)     // 4352
#define SMEM_F (STAGES * (A_STAGE_F + B_STAGE_F) + 1024 + 1024)
#define SMEM_BYTES (SMEM_F * 4)

// -------- scratch (static device globals) --------
__device__ float g_gating[BATCH * NEXP];
__device__ float g_cpack[(size_t)BATCH * IN_DIM];   // 10.5 MB, fragment-packed tf32

// ======================= helpers =======================
__device__ __forceinline__ uint32_t smem_u32(const void* p) {
    uint32_t a;
    asm("{ .reg .u64 t; cvta.to.shared.u64 t, %1; cvt.u32.u64 %0, t; }" : "=r"(a) : "l"(p));
    return a;
}
__device__ __forceinline__ float tf32_rna(float x) {
    float y;
    asm("cvt.rna.tf32.f32 %0, %1;" : "=f"(y) : "f"(x));
    return y;
}
#define CP16(dst, src) \
    asm volatile("cp.async.cg.shared.global [%0], [%1], 16;" :: "r"(dst), "l"(src))
#define CP_COMMIT() asm volatile("cp.async.commit_group;" ::: "memory")
#define CP_WAIT(n)  asm volatile("cp.async.wait_group %0;" :: "n"(n) : "memory")

__device__ __forceinline__ void mma_tf32(float* d, const uint32_t* a, const uint32_t* b) {
    asm volatile(
        "mma.sync.aligned.m16n8k8.row.col.f32.tf32.tf32.f32 "
        "{%0,%1,%2,%3}, {%4,%5,%6,%7}, {%8,%9}, {%0,%1,%2,%3};"
        : "+f"(d[0]), "+f"(d[1]), "+f"(d[2]), "+f"(d[3])
        : "r"(a[0]), "r"(a[1]), "r"(a[2]), "r"(a[3]), "r"(b[0]), "r"(b[1]));
}

// ======================= Prologue =======================
// One block per batch row b: label-embed, concat, gating (sigmoid),
// and write c (tf32-rounded) PRE-PACKED in m16n8k8 A-fragment order:
//   float idx = ((mt*320 + kb)*8 + mb16)*128 + lane*4 + v
//   mt=b/128, mb16=(b%128)/16, r16=b%16, kb=i/8, kk=i%8
//   lane=(r16%8)*4 + (kk%4),  v=(r16/8) + 2*(kk/4)
__global__ __launch_bounds__(256) void moe_prologue(
    const float* __restrict__ feat, const float* __restrict__ labels,
    const float* __restrict__ lemb, const float* __restrict__ gw,
    const float* __restrict__ gb)
{
    int b = blockIdx.x, tid = threadIdx.x;
    __shared__ float s_lab[LDIM];
    __shared__ float s_c[IN_DIM];
    __shared__ float s_red[NEXP * 8];

    if (tid < LDIM) s_lab[tid] = labels[(size_t)b * LDIM + tid];
    const float4* f4 = reinterpret_cast<const float4*>(feat + (size_t)b * FDIM);
    float4* c4 = reinterpret_cast<float4*>(s_c);
    for (int i = tid; i < FDIM / 4; i += 256) c4[i] = f4[i];
    __syncthreads();

    for (int j = tid; j < EDIM; j += 256) {
        float acc = 0.f;
        #pragma unroll 8
        for (int l = 0; l < LDIM; ++l) acc += s_lab[l] * lemb[l * EDIM + j];
        s_c[FDIM + j] = acc;
    }
    __syncthreads();

    // gating
    float acc[NEXP];
    #pragma unroll
    for (int e = 0; e < NEXP; ++e) acc[e] = 0.f;
    for (int k = tid; k < IN_DIM; k += 256) {
        float cv = s_c[k];
        const float4* w4 = reinterpret_cast<const float4*>(gw + (size_t)k * NEXP);
        float4 w0 = w4[0], w1 = w4[1];
        acc[0] += cv * w0.x; acc[1] += cv * w0.y; acc[2] += cv * w0.z; acc[3] += cv * w0.w;
        acc[4] += cv * w1.x; acc[5] += cv * w1.y; acc[6] += cv * w1.z; acc[7] += cv * w1.w;
    }
    int lane = tid & 31, wid = tid >> 5;
    #pragma unroll
    for (int e = 0; e < NEXP; ++e) {
        float v = acc[e];
        v += __shfl_xor_sync(0xffffffff, v, 16);
        v += __shfl_xor_sync(0xffffffff, v, 8);
        v += __shfl_xor_sync(0xffffffff, v, 4);
        v += __shfl_xor_sync(0xffffffff, v, 2);
        v += __shfl_xor_sync(0xffffffff, v, 1);
        if (lane == 0) s_red[e * 8 + wid] = v;
    }
    __syncthreads();
    if (tid < NEXP) {
        float z = gb[tid];
        #pragma unroll
        for (int w = 0; w < 8; ++w) z += s_red[tid * 8 + w];
        g_gating[(size_t)b * NEXP + tid] = 1.f / (1.f + __expf(-z));
    }

    // packed tf32 c write: off = lane*4 + v  (floats), guaranteed <= 127
    int mt = b >> 7, rl = b & 127, mb = rl >> 4, r16 = rl & 15;
    int row_part = (r16 & 7) * 16 + (r16 >> 3);   // lane(row)*4 + v(row-bit)
    for (int i = tid; i < IN_DIM; i += 256) {
        int kb = i >> 3, kk = i & 7;
        int off = row_part + (kk & 3) * 4 + (kk >> 2) * 2;  // + lane(k)*4 + v(k-bit)
        size_t idx = ((size_t)((mt * 320 + kb) * 8 + mb)) * 128 + off;
        g_cpack[idx] = tf32_rna(s_c[i]);
    }
}

// ======================= Main GEMM kernel =======================
// out[1024,2048] = sum_e g[:,e] * (c @ W_e) + (sum_e g[:,e]*bias_e)
// CTA 128x128, BK=32, 4-stage cp.async, 8 warps (2m x 4n), m16n8k8 tf32.
// Expert-outer K loop; dual accumulators; gate applied at expert boundaries.
__global__ __launch_bounds__(256, 1) void moe_gemm(
    const float* __restrict__ expert_w, const float* __restrict__ expert_b,
    float* __restrict__ out)
{
    extern __shared__ float smem[];
    float* As     = smem;                          // STAGES*4096
    float* Bs     = As + STAGES * A_STAGE_F;       // STAGES*4352
    float* g_s    = Bs + STAGES * B_STAGE_F;       // 128*8
    float* bias_s = g_s + 1024;                    // 8*128

    const int tid = threadIdx.x;
    const int wid = tid >> 5, lane = tid & 31;
    const int wm = wid & 1, wn = wid >> 1;         // warp tile 64m x 32n
    const int n0 = blockIdx.x * BN;
    const int m0 = blockIdx.y * BM;
    const int mt = blockIdx.y;                     // BM==128

    const uint32_t As_a = smem_u32(As);
    const uint32_t Bs_a = smem_u32(Bs);

    float acc_o[4][4][4];
    float acc_e[4][4][4];
    #pragma unroll
    for (int f = 0; f < 4; ++f)
        #pragma unroll
        for (int g = 0; g < 4; ++g)
            #pragma unroll
            for (int c = 0; c < 4; ++c) { acc_o[f][g][c] = 0.f; acc_e[f][g][c] = 0.f; }

    // ---- stage issue ----
    auto issue = [&](int slot, int it) {
        int e = it / ITER_PER_E, ii = it % ITER_PER_E;
        // A: 16KB contiguous from packed c
        const float* asrc = g_cpack + ((size_t)(mt * 320 + ii * 4)) * 1024;
        uint32_t adst = As_a + slot * (A_STAGE_F * 4);
        #pragma unroll
        for (int j = 0; j < 4; ++j) {
            int u = tid + 256 * j;
            CP16(adst + u * 16, asrc + u * 4);
        }
        // B: 32 rows x 512B from W
        const float* bsrc = expert_w + ((size_t)e * IN_DIM + ii * BK) * ODIM + n0;
        uint32_t bdst = Bs_a + slot * (B_STAGE_F * 4);
        #pragma unroll
        for (int j = 0; j < 4; ++j) {
            int u = tid + 256 * j;
            int r = u >> 5, ch = u & 31;
            CP16(bdst + r * (B_ROW_F * 4) + ch * 16, bsrc + (size_t)r * ODIM + ch * 4);
        }
    };

    // prefetch 3 stages
    issue(0, 0); CP_COMMIT();
    issue(1, 1); CP_COMMIT();
    issue(2, 2); CP_COMMIT();

    // load gating + bias slices while prefetch flies
    for (int i = tid; i < BM * NEXP; i += 256) {
        int r = i >> 3, e = i & 7;
        g_s[r * 8 + e] = g_gating[(size_t)(m0 + r) * NEXP + e];
    }
    for (int i = tid; i < NEXP * BN; i += 256) {
        int e = i >> 7, c = i & 127;
        bias_s[e * 128 + c] = expert_b[(size_t)e * ODIM + n0 + c];
    }

    const int nrow = lane >> 2;   // 0..7
    const int kcol = lane & 3;    // 0..3

    for (int it = 0; it < NIT; ++it) {
        int slot = it & (STAGES - 1);
        // oldest of the 3 pending groups is stage `it`
        CP_WAIT(2);
        __syncthreads();
        // slot (it-1)&3 == (it+3)&3 was fully consumed before the sync above
        int nxt = it + 3;
        if (nxt < NIT) issue(nxt & (STAGES - 1), nxt);
        CP_COMMIT();

        // ---- compute chunk it from SMEM ----
        const uint32_t abase = As_a + slot * (A_STAGE_F * 4) + (wm * 4) * 512 + lane * 16;
        const float* bst = Bs + slot * B_STAGE_F;
        #pragma unroll
        for (int k = 0; k < 4; ++k) {
            uint32_t a[4][4];
            #pragma unroll
            for (int f = 0; f < 4; ++f) {
                uint4 v = *reinterpret_cast<const uint4*>(
                    reinterpret_cast<const char*>(As) + (abase - As_a) + k * 4096 + f * 512);
                a[f][0] = v.x; a[f][1] = v.y; a[f][2] = v.z; a[f][3] = v.w;
            }
            uint32_t b[4][2];
            #pragma unroll
            for (int g = 0; g < 4; ++g) {
                int nidx = wn * 32 + g * 8 + nrow;
                b[g][0] = __float_as_uint(bst[(k * 8 + kcol) * B_ROW_F + nidx]);
                b[g][1] = __float_as_uint(bst[(k * 8 + kcol + 4) * B_ROW_F + nidx]);
            }
            #pragma unroll
            for (int f = 0; f < 4; ++f)
                #pragma unroll
                for (int g = 0; g < 4; ++g)
                    mma_tf32(acc_e[f][g], a[f], b[g]);
        }

        // ---- expert boundary: gate-scale into output accumulator ----
        if ((it % ITER_PER_E) == ITER_PER_E - 1) {
            int e = it / ITER_PER_E;
            #pragma unroll
            for (int f = 0; f < 4; ++f) {
                int rl = wm * 64 + f * 16 + nrow;
                float gl = g_s[rl * 8 + e];
                float gh = g_s[(rl + 8) * 8 + e];
                #pragma unroll
                for (int g = 0; g < 4; ++g) {
                    acc_o[f][g][0] += gl * acc_e[f][g][0];
                    acc_o[f][g][1] += gl * acc_e[f][g][1];
                    acc_o[f][g][2] += gh * acc_e[f][g][2];
                    acc_o[f][g][3] += gh * acc_e[f][g][3];
                    acc_e[f][g][0] = 0.f; acc_e[f][g][1] = 0.f;
                    acc_e[f][g][2] = 0.f; acc_e[f][g][3] = 0.f;
                }
            }
        }
    }

    // ---- epilogue: gated bias + store ----
    #pragma unroll
    for (int f = 0; f < 4; ++f) {
        int rl = wm * 64 + f * 16 + nrow;
        int rh = rl + 8;
        #pragma unroll
        for (int g = 0; g < 4; ++g) {
            int cb = wn * 32 + g * 8 + 2 * kcol;
            float bl0 = 0.f, bl1 = 0.f, bh0 = 0.f, bh1 = 0.f;
            #pragma unroll
            for (int e = 0; e < NEXP; ++e) {
                float gle = g_s[rl * 8 + e], ghe = g_s[rh * 8 + e];
                float b0v = bias_s[e * 128 + cb], b1v = bias_s[e * 128 + cb + 1];
                bl0 += gle * b0v; bl1 += gle * b1v;
                bh0 += ghe * b0v; bh1 += ghe * b1v;
            }
            float2 lo = make_float2(acc_o[f][g][0] + bl0, acc_o[f][g][1] + bl1);
            float2 hi = make_float2(acc_o[f][g][2] + bh0, acc_o[f][g][3] + bh1);
            *reinterpret_cast<float2*>(out + (size_t)(m0 + rl) * ODIM + n0 + cb) = lo;
            *reinterpret_cast<float2*>(out + (size_t)(m0 + rh) * ODIM + n0 + cb) = hi;
        }
    }
}

// ======================= launch =======================
extern "C" void kernel_launch(void* const* d_in, const int* in_sizes, int n_in,
                              void* d_out, int out_size) {
    const float* feat   = (const float*)d_in[0];
    const float* labels = (const float*)d_in[1];
    const float* lemb   = (const float*)d_in[2];
    const float* gw     = (const float*)d_in[3];
    const float* gb     = (const float*)d_in[4];
    const float* ew     = (const float*)d_in[5];
    const float* eb     = (const float*)d_in[6];
    float* out = (float*)d_out;

    moe_prologue<<<BATCH, 256>>>(feat, labels, lemb, gw, gb);

    cudaFuncSetAttribute(moe_gemm, cudaFuncAttributeMaxDynamicSharedMemorySize, SMEM_BYTES);
    dim3 grid(ODIM / BN, BATCH / BM);   // 16 x 8 = 128 CTAs
    moe_gemm<<<grid, 256, SMEM_BYTES>>>(ew, eb, out);
}